// round 15
// baseline (speedup 1.0000x reference)
#include <cuda_runtime.h>
#include <math.h>

// Problem shape constants
#define BB   8
#define HHH  1024
#define WWW  1024
#define TW   128     // tile width  (output pixels)
#define TH   16      // tile height (output pixels)
#define NTHREADS 256

// Accumulator layout (doubles):
//  [0]        focal sum  (Σ over all 3 slices, all pixels, of -log(pt+eps))
//  [1]        edge  sum  (Σ of -log(pt+eps) * |t - ave|)
//  [2  + s*8 + b]  Σ p1          per slice s, batch b
//  [26 + s*8 + b]  Σ p1 * t      per slice s, batch b
//  [50 + b]        Σ t           per batch b
// Zero-initialized at module load; finalize_kernel re-zeroes after reading,
// so every graph replay starts from a clean state.
__device__ double g_acc[58];

// Fast reciprocal on the FMA pipe (no MUFU): bit-trick seed + 2 Newton steps.
// Max rel err ~6e-6 (one-sided), valid for all normal positive floats.
__device__ __forceinline__ float frcp2(float x) {
    float y = __uint_as_float(0x7EF311C3u - __float_as_uint(x));
    y = y * (2.0f - x * y);
    y = y * (2.0f - x * y);
    return y;
}

__global__ __launch_bounds__(NTHREADS, 4)
void main_kernel(const float* __restrict__ pred,
                 const float* __restrict__ diss,
                 const int*   __restrict__ target)
{
    // target tile (as float) with halo 3: rows [h0-3, h0+TH+3), cols [w0-3, w0+TW+3)
    __shared__ float raw[22][136];   // 22 rows x 134 used cols (pad to 136)
    __shared__ float rs5[20][128];   // 5-wide horizontal sums, rows raw[1..20]
    __shared__ float red[9][8];

    const int b  = blockIdx.z;
    const int w0 = blockIdx.x * TW;
    const int h0 = blockIdx.y * TH;
    const int tx = threadIdx.x;          // 0..31
    const int ty = threadIdx.y;          // 0..7
    const int tid = ty * 32 + tx;

    const size_t hw = (size_t)HHH * WWW;
    const float* pl[6];
    pl[0] = pred + ((size_t)b        * 2 + 0) * hw;   // a0
    pl[1] = pred + ((size_t)b        * 2 + 1) * hw;   // a1
    pl[2] = pred + ((size_t)(8 + b)  * 2 + 0) * hw;   // q0
    pl[3] = pred + ((size_t)(8 + b)  * 2 + 1) * hw;   // q1
    pl[4] = diss + ((size_t)b        * 2 + 0) * hw;   // c0
    pl[5] = diss + ((size_t)b        * 2 + 1) * hw;   // c1

    // ==== PREFETCH: issue ALL 48 plane loads before the smem stages.  ====
    // They are independent of the target tile; the two smem stages below
    // (~400-500 cyc of LDG+LDS+2 BAR) then run UNDER the DRAM latency.
    // 48 outstanding LDG/warp < M_max(~55). Constant indices keep L in regs.
    float L[2][6][4];
    #pragma unroll
    for (int rr = 0; rr < 2; rr++) {
        const size_t base = (size_t)(h0 + ty * 2 + rr) * WWW + w0 + tx;
        #pragma unroll
        for (int s = 0; s < 6; s++) {
            #pragma unroll
            for (int j = 0; j < 4; j++)
                L[rr][s][j] = __ldcs(pl[s] + base + 32 * j);
        }
    }

    const int* tgt_b = target + (size_t)b * hw;

    // ---- stage 0: load target tile (zero-padded SAME boundary) as float ----
    for (int i = tid; i < 22 * 134; i += NTHREADS) {
        int hh = i / 134, cc = i - hh * 134;
        int gh = h0 - 3 + hh, gw = w0 - 3 + cc;
        float v = 0.f;
        if (gh >= 0 && gh < HHH && gw >= 0 && gw < WWW)
            v = (float)tgt_b[(size_t)gh * WWW + gw];
        raw[hh][cc] = v;
    }
    __syncthreads();

    // ---- stage 1: horizontal 5-sums (lane-linear -> conflict-free) ----
    for (int i = tid; i < 20 * 128; i += NTHREADS) {
        int r = i >> 7, w = i & 127;
        rs5[r][w] = raw[r+1][w+1] + raw[r+1][w+2] + raw[r+1][w+3]
                  + raw[r+1][w+4] + raw[r+1][w+5];
    }
    __syncthreads();

    float facc = 0.f, eacc = 0.f;
    float p1s0 = 0.f, p1s1 = 0.f, p1s2 = 0.f;
    float p1t0 = 0.f, p1t1 = 0.f, p1t2 = 0.f;
    float tcf  = 0.f;
    float s5v[4];   // per-j vertical 5-sum of rs5, slid between the two rows
                    // (exact: small-integer values are exact in fp32)

    #pragma unroll
    for (int rr = 0; rr < 2; rr++) {
        const int oh = ty * 2 + rr;            // 0..15 within tile
        const int hr = oh + 3;

        #pragma unroll
        for (int j = 0; j < 4; j++) {
            const int c  = tx + 32 * j;    // output col within tile (lane-consecutive)
            const int wr = c + 3;          // raw col of center

            const float tf = raw[hr][wr];
            // Vertical 5-sum of rs5: full sum on first row, sliding update on
            // the second (window shifts down by 1: +row oh+4, -row oh-1).
            if (rr == 0)
                s5v[j] = rs5[oh  ][c] + rs5[oh+1][c] + rs5[oh+2][c]
                       + rs5[oh+3][c] + rs5[oh+4][c];
            else
                s5v[j] += rs5[oh+4][c] - rs5[oh-1][c];

            // 29-cell circular mask = 5x5 box + (±3,0) + (0,±3)
            float s29 = s5v[j]
                      + raw[hr][c] + raw[hr][c+6]    // (0,-3),(0,+3)
                      + raw[oh][wr] + raw[oh+6][wr]; // (-3,0),(+3,0)

            const float at = fabsf(tf - s29 * (1.0f / 29.0f));
            const bool  t1 = tf > 0.5f;

            // Merged 3-slice log:
            //   slices 0,1 (softmax): nl_s = log(1+e^{d_s}) - (t?0:d_s),
            //     valid since p >> eps (|d| <~ 9; est. abs err ~2e-6)
            //   slice 2 (raw probs):  nl_2 = -log(pt2 + eps)
            //   nl_total = log(z0*z1/(pt2+eps)) - (t?0:(d0+d1)),  z_s = 1+e^{d_s}
            float d0 = L[rr][0][j] - L[rr][1][j];
            float d1 = L[rr][2][j] - L[rr][3][j];
            float e0 = __expf(d0);
            float e1 = __expf(d1);
            float z0 = 1.0f + e0;
            float z1 = 1.0f + e1;
            float zz = z0 * z1;

            float pt2 = (t1 ? L[rr][5][j] : L[rr][4][j]) + 1e-10f;
            float nl  = __logf(zz * frcp2(pt2));
            nl -= t1 ? 0.0f : (d0 + d1);

            float w   = frcp2(zz);       // 1/(z0*z1)
            float p10 = z1 * w;          // 1/z0
            float p11 = z0 * w;          // 1/z1
            float p12 = L[rr][5][j];

            facc += nl;  eacc += nl * at;
            p1s0 += p10; p1s1 += p11; p1s2 += p12;
            p1t0 += t1 ? p10 : 0.0f;
            p1t1 += t1 ? p11 : 0.0f;
            p1t2 += t1 ? p12 : 0.0f;
            tcf  += tf;
        }
    }

    // ---- block reduction: warp shuffles, then 8 warp partials per value ----
    float vals[9] = {facc, eacc, p1s0, p1s1, p1s2, p1t0, p1t1, p1t2, tcf};
    #pragma unroll
    for (int k = 0; k < 9; k++) {
        float v = vals[k];
        #pragma unroll
        for (int o = 16; o; o >>= 1) v += __shfl_xor_sync(0xFFFFFFFFu, v, o);
        if ((tid & 31) == 0) red[k][tid >> 5] = v;
    }
    __syncthreads();

    if (tid < 9) {
        float s = 0.f;
        #pragma unroll
        for (int w = 0; w < 8; w++) s += red[tid][w];
        int addr;
        if      (tid == 0) addr = 0;
        else if (tid == 1) addr = 1;
        else if (tid <  5) addr = 2  + (tid - 2) * 8 + b;
        else if (tid <  8) addr = 26 + (tid - 5) * 8 + b;
        else               addr = 50 + b;
        atomicAdd(&g_acc[addr], (double)s);
    }
}

// One-warp finalize, ALL-FP32 math (FP64 soft-div/log cost ~5us before).
__global__ __launch_bounds__(32)
void finalize_kernel(const float* __restrict__ diff,
                     const float* __restrict__ sigma,
                     float* __restrict__ out)
{
    const int lane = threadIdx.x;

    // Dice term for (s,b) pair on lanes 0..23 (loads issue in parallel):
    float term = 0.f;
    if (lane < 24) {
        int s = lane >> 3, bb = lane & 7;
        float I = (float)g_acc[26 + s * 8 + bb];
        float U = (float)g_acc[2  + s * 8 + bb] + (float)g_acc[50 + bb];
        term = 2.0f * I * frcp2(U + 1e-10f);
    }
    float fsum = (float)g_acc[0];
    float esum = (float)g_acc[1];

    #pragma unroll
    for (int o = 16; o; o >>= 1)
        term += __shfl_xor_sync(0xFFFFFFFFu, term, o);
    // dice = Σ_s (1 - mean_b(term)) = 3 - term_total / 8
    float dice = 3.0f - term * 0.125f;

    if (lane == 0) {
        float s0 = sigma[0] * sigma[0];
        float s1 = sigma[1] * sigma[1];
        float s2 = sigma[2] * sigma[2];

        const float invNp = 1.0f / (8.0f * 1024.0f * 1024.0f);

        float loss = fsum * invNp * frcp2(s0)
                   + dice * frcp2(s1)
                   + esum * invNp * frcp2(s2)
                   + diff[0]
                   + 0.5f * (__logf(s0) + __logf(s1) + __logf(s2));
        out[0] = loss;
    }

    // Re-zero accumulators for next replay (all g_acc reads above completed
    // in-warp; shuffle reduction synchronized the warp).
    __syncwarp();
    if (lane < 29) { g_acc[lane] = 0.0; g_acc[lane + 29] = 0.0; }
}

extern "C" void kernel_launch(void* const* d_in, const int* in_sizes, int n_in,
                              void* d_out, int out_size)
{
    const float* pred   = (const float*)d_in[0];  // (2,8,2,1024,1024) f32
    const float* diss   = (const float*)d_in[1];  // (1,8,2,1024,1024) f32
    const int*   target = (const int*)  d_in[2];  // (8,1024,1024) i32
    const float* diff   = (const float*)d_in[3];  // scalar f32
    const float* sigma  = (const float*)d_in[4];  // (3,) f32
    float* out = (float*)d_out;

    dim3 grid(WWW / TW, HHH / TH, BB);   // (8, 64, 8) = 4096 blocks
    dim3 block(32, 8);
    main_kernel<<<grid, block>>>(pred, diss, target);
    finalize_kernel<<<1, 32>>>(diff, sigma, out);
}